// round 3
// baseline (speedup 1.0000x reference)
#include <cuda_runtime.h>

// N=262144 rows, K=512 codes, D=64 dims.
// Output (fp32, concatenated, tuple order): loss(1) | quantized(N*64) |
// perplexity(1) | encodings one-hot(N*512) | encoding_indices(N).
// offQ=1 (4B-aligned only), offE=N*64+2 (8B-aligned). No float4 on out.
// labels buffer is INT32 (jax x64 disabled downgrades int64 -> int32).

#define KC 512
#define DC 64
#define TPB 512

static __device__ float g_embn[KC * DC];     // normalized embedding, [k][d]
static __device__ float g_partials[1024];    // per-block picked sums

// ---------------------------------------------------------------------------
// Kernel 1: normalize embedding rows
// ---------------------------------------------------------------------------
__global__ void vq_prep(const float* __restrict__ emb) {
    int k = threadIdx.x;
    if (k >= KC) return;
    float v[DC];
    float s = 0.f;
#pragma unroll
    for (int d = 0; d < DC; d++) {
        v[d] = emb[k * DC + d];
        s = fmaf(v[d], v[d], s);
    }
    float den = fmaxf(sqrtf(s), 1e-12f);
#pragma unroll
    for (int d = 0; d < DC; d++) g_embn[k * DC + d] = v[d] / den;
}

// ---------------------------------------------------------------------------
// Kernel 2: main
// ---------------------------------------------------------------------------
__global__ __launch_bounds__(TPB, 1) void vq_main(
    const float* __restrict__ xin, const int* __restrict__ labels,
    const float* __restrict__ emb, float* __restrict__ out,
    int N, long long offQ, long long offE, long long offI, long long outTotal)
{
    extern __shared__ float embT[];           // [DC][KC] 64x512 f32 = 128 KB
    __shared__ int   sbidx[TPB];
    __shared__ float sred[TPB];

    const int tid = threadIdx.x;

    // Cooperative transposed load of normalized embedding
#pragma unroll 4
    for (int i = tid; i < KC * DC; i += TPB) {
        int k = i & (KC - 1);
        int d = i >> 9;
        embT[d * KC + k] = g_embn[k * DC + d];
    }
    __syncthreads();

    const int row = blockIdx.x * TPB + tid;
    float picked = 0.f;
    int   bidx   = 0;

    if (row < N) {
        const float* xr = xin + (size_t)row * DC;
        float x[DC];
        float nrm2 = 0.f;
#pragma unroll
        for (int d = 0; d < DC; d += 4) {
            float4 v = *reinterpret_cast<const float4*>(xr + d);   // xin aligned
            x[d] = v.x; x[d + 1] = v.y; x[d + 2] = v.z; x[d + 3] = v.w;
            nrm2 = fmaf(v.x, v.x, nrm2);
            nrm2 = fmaf(v.y, v.y, nrm2);
            nrm2 = fmaf(v.z, v.z, nrm2);
            nrm2 = fmaf(v.w, v.w, nrm2);
        }
        const float xnorm = fmaxf(sqrtf(nrm2), 1e-12f);

        float best  = -3.402823466e38f, best2 = -3.402823466e38f;
        int   bidx2 = 0;

        // K in tiles of 16 (8 packed f32x2 accumulators); unnormalized x
        // (positive scaling preserves ordering; near-ties refined below)
        for (int k0 = 0; k0 < KC; k0 += 16) {
            unsigned long long acc[8];
#pragma unroll
            for (int q = 0; q < 8; q++) acc[q] = 0ull;

#pragma unroll
            for (int d = 0; d < DC; d++) {
                unsigned long long xd;
                asm("mov.b64 %0, {%1, %1};" : "=l"(xd) : "f"(x[d]));
                const ulonglong2* ep = reinterpret_cast<const ulonglong2*>(
                    embT + d * KC + k0);                 // 16B-aligned smem
#pragma unroll
                for (int q = 0; q < 4; q++) {
                    ulonglong2 e2 = ep[q];
                    asm("fma.rn.f32x2 %0, %1, %2, %0;"
                        : "+l"(acc[2 * q]) : "l"(xd), "l"(e2.x));
                    asm("fma.rn.f32x2 %0, %1, %2, %0;"
                        : "+l"(acc[2 * q + 1]) : "l"(xd), "l"(e2.y));
                }
            }
#pragma unroll
            for (int q = 0; q < 8; q++) {
                float lo, hi;
                asm("mov.b64 {%0, %1}, %2;" : "=f"(lo), "=f"(hi) : "l"(acc[q]));
                int kk = k0 + 2 * q;
                if (lo > best)       { best2 = best; bidx2 = bidx; best = lo; bidx = kk; }
                else if (lo > best2) { best2 = lo;   bidx2 = kk; }
                if (hi > best)       { best2 = best; bidx2 = bidx; best = hi; bidx = kk + 1; }
                else if (hi > best2) { best2 = hi;   bidx2 = kk + 1; }
            }
        }

        // Near-tie refinement in fp64 on fp32-rounded normalized x (matches
        // the reference's rounding point). Rare path (~0.25% of rows).
        if (best - best2 < 1e-4f * xnorm) {
            double s1 = 0.0, s2 = 0.0;
#pragma unroll
            for (int d = 0; d < DC; d++) {
                float xh = __fdiv_rn(x[d], xnorm);
                s1 += (double)xh * (double)embT[d * KC + bidx];
                s2 += (double)xh * (double)embT[d * KC + bidx2];
            }
            if (s2 > s1 || (s2 == s1 && bidx2 < bidx)) bidx = bidx2;
        }

        // label-picked cosine (labels are INT32; clamp defensively)
        int lab = labels[row];
        lab = max(0, min(KC - 1, lab));
        float yl = 0.f;
#pragma unroll
        for (int d = 0; d < DC; d++) yl = fmaf(x[d], embT[d * KC + lab], yl);
        picked = yl / xnorm;

        // indices output (coalesced scalar)
        if (offI + N <= outTotal) out[offI + row] = (float)bidx;
    }

    sbidx[tid] = bidx;
    __syncthreads();

    // ---- Block-cooperative, coalesced output streaming ----
    // quantized (odd element base -> scalar stores, still coalesced)
    if (offQ + (long long)N * DC <= outTotal) {
        long long qbase = offQ + (long long)blockIdx.x * TPB * DC;
        const int total = TPB * DC;  // 32768
#pragma unroll 4
        for (int j = tid; j < total; j += TPB) {
            int r = j >> 6;
            int d = j & 63;
            out[qbase + j] = __ldg(&emb[sbidx[r] * DC + d]);
        }
    }
    // encodings: one-hot computed inline, float2 stores (offE is even)
    if (offE + (long long)N * KC <= outTotal) {
        long long ebase = offE + (long long)blockIdx.x * TPB * KC;
        float2* eo2 = reinterpret_cast<float2*>(out + ebase);
        const int total2 = TPB * KC / 2;  // 131072
#pragma unroll 4
        for (int j = tid; j < total2; j += TPB) {
            int r = j >> 8;               // 256 float2 per row
            int c = (j & 255) << 1;
            int b = sbidx[r];
            float2 v;
            v.x = (c     == b) ? 1.0f : 0.0f;
            v.y = (c + 1 == b) ? 1.0f : 0.0f;
            eo2[j] = v;
        }
    }

    // Deterministic block reduction of picked
    sred[tid] = picked;
    __syncthreads();
#pragma unroll
    for (int s = TPB / 2; s > 0; s >>= 1) {
        if (tid < s) sred[tid] += sred[tid + s];
        __syncthreads();
    }
    if (tid == 0) g_partials[blockIdx.x] = sred[0];
}

// ---------------------------------------------------------------------------
// Kernel 3: finalize
// ---------------------------------------------------------------------------
__global__ void vq_fin(float* __restrict__ out, long long offP, int nblocks,
                       int N, long long outTotal) {
    __shared__ double sh[1024];
    int t = threadIdx.x;
    double v = 0.0;
    for (int i = t; i < nblocks; i += 1024) v += (double)g_partials[i];
    sh[t] = v;
    __syncthreads();
    for (int s = 512; s > 0; s >>= 1) {
        if (t < s) sh[t] += sh[t + s];
        __syncthreads();
    }
    if (t == 0) {
        if (outTotal > 0)    out[0]    = (float)(1.0 - sh[0] / (double)N);
        if (offP < outTotal) out[offP] = 1.0f;   // perplexity
    }
}

// ---------------------------------------------------------------------------
extern "C" void kernel_launch(void* const* d_in, const int* in_sizes, int n_in,
                              void* d_out, int out_size) {
    const float* xin    = (const float*)d_in[0];
    const int*   labels = (const int*)d_in[1];     // int32 (jax x64 off)
    const float* emb    = (const float*)d_in[2];
    float*       out    = (float*)d_out;

    int N = in_sizes[1];   // labels count == row count
    (void)n_in;

    long long outTotal = (long long)out_size;
    long long offQ = 1;
    long long offP = offQ + (long long)N * DC;
    long long offE = offP + 1;
    long long offI = offE + (long long)N * KC;

    int grid = (N + TPB - 1) / TPB;
    int smem = KC * DC * (int)sizeof(float);   // 131072 B

    cudaFuncSetAttribute(vq_main, cudaFuncAttributeMaxDynamicSharedMemorySize, smem);

    vq_prep<<<1, 512>>>(emb);
    vq_main<<<grid, TPB, smem>>>(xin, labels, emb, out, N, offQ, offE, offI, outTotal);
    vq_fin<<<1, 1024>>>(out, offP, grid, N, outTotal);
}

// round 4
// speedup vs baseline: 1.3375x; 1.3375x over previous
#include <cuda_runtime.h>

// N=262144 rows, K=512 codes, D=64 dims.
// Output (fp32, concat): loss(1) | quantized(N*64) | perplexity(1) |
// encodings(N*512) | indices(N).  offQ=1 (4B align), offE even (8B align).
// labels are INT32.

#define KC 512
#define DC 64
#define TPB 256          // threads per block
#define RPB 512          // rows per block (2 rows per thread)

static __device__ float g_embnT[DC * KC];    // normalized embedding, [d][k]
static __device__ float g_partials[1024];

// ---------------------------------------------------------------------------
// Kernel 1: normalize embedding rows, store TRANSPOSED [d][k]
// ---------------------------------------------------------------------------
__global__ void vq_prep(const float* __restrict__ emb) {
    int k = blockIdx.x * blockDim.x + threadIdx.x;
    if (k >= KC) return;
    float v[DC];
    float s = 0.f;
#pragma unroll
    for (int d = 0; d < DC; d++) {
        v[d] = emb[k * DC + d];
        s = fmaf(v[d], v[d], s);
    }
    float den = fmaxf(sqrtf(s), 1e-12f);
#pragma unroll
    for (int d = 0; d < DC; d++) g_embnT[d * KC + k] = v[d] / den;
}

// ---------------------------------------------------------------------------
// Kernel 2: main.  2 rows per thread; block covers 512 rows.
// ---------------------------------------------------------------------------
__global__ __launch_bounds__(TPB) void vq_main(
    const float* __restrict__ xin, const int* __restrict__ labels,
    const float* __restrict__ emb, float* __restrict__ out,
    int N, long long offQ, long long offE, long long offI, long long outTotal)
{
    extern __shared__ float embT[];          // [DC][KC] = 128 KB
    __shared__ int   sbidx[RPB];
    __shared__ float sred[TPB];

    const int tid = threadIdx.x;

    // Linear coalesced copy of pre-transposed normalized embedding
    {
        const float4* src = reinterpret_cast<const float4*>(g_embnT);
        float4* dst = reinterpret_cast<float4*>(embT);
#pragma unroll
        for (int i = tid; i < KC * DC / 4; i += TPB) dst[i] = src[i];
    }
    __syncthreads();

    const long long rowBase = (long long)blockIdx.x * RPB;
    const int row0 = (int)rowBase + tid;
    const int row1 = row0 + TPB;
    const bool v0 = row0 < N, v1 = row1 < N;

    float x0[DC], x1[DC];
    float n0 = 0.f, n1 = 0.f;
    if (v0) {
        const float4* xr = reinterpret_cast<const float4*>(xin + (size_t)row0 * DC);
#pragma unroll
        for (int d4 = 0; d4 < DC / 4; d4++) {
            float4 v = xr[d4];
            x0[4*d4] = v.x; x0[4*d4+1] = v.y; x0[4*d4+2] = v.z; x0[4*d4+3] = v.w;
            n0 = fmaf(v.x, v.x, n0); n0 = fmaf(v.y, v.y, n0);
            n0 = fmaf(v.z, v.z, n0); n0 = fmaf(v.w, v.w, n0);
        }
    } else {
#pragma unroll
        for (int d = 0; d < DC; d++) x0[d] = 0.f;
    }
    if (v1) {
        const float4* xr = reinterpret_cast<const float4*>(xin + (size_t)row1 * DC);
#pragma unroll
        for (int d4 = 0; d4 < DC / 4; d4++) {
            float4 v = xr[d4];
            x1[4*d4] = v.x; x1[4*d4+1] = v.y; x1[4*d4+2] = v.z; x1[4*d4+3] = v.w;
            n1 = fmaf(v.x, v.x, n1); n1 = fmaf(v.y, v.y, n1);
            n1 = fmaf(v.z, v.z, n1); n1 = fmaf(v.w, v.w, n1);
        }
    } else {
#pragma unroll
        for (int d = 0; d < DC; d++) x1[d] = 0.f;
    }
    const float xn0 = fmaxf(sqrtf(n0), 1e-12f);
    const float xn1 = fmaxf(sqrtf(n1), 1e-12f);

    float best0 = -3.402823466e38f, sec0 = -3.402823466e38f;
    float best1 = -3.402823466e38f, sec1 = -3.402823466e38f;
    int   bidx0 = 0, bidx20 = 0, bidx1 = 0, bidx21 = 0;

    // K tiles of 16 codes; 8 f32x2 accumulators per row.
#pragma unroll 1
    for (int k0 = 0; k0 < KC; k0 += 16) {
        unsigned long long a0[8], a1[8];
#pragma unroll
        for (int q = 0; q < 8; q++) { a0[q] = 0ull; a1[q] = 0ull; }

#pragma unroll
        for (int d = 0; d < DC; d++) {
            unsigned long long xd0, xd1;
            asm("mov.b64 %0, {%1, %1};" : "=l"(xd0) : "f"(x0[d]));
            asm("mov.b64 %0, {%1, %1};" : "=l"(xd1) : "f"(x1[d]));
            const ulonglong2* ep =
                reinterpret_cast<const ulonglong2*>(embT + d * KC + k0);
            ulonglong2 eA = ep[0];   // codes k0+0..3
            ulonglong2 eB = ep[1];   // codes k0+4..7
            ulonglong2 eC = ep[2];
            ulonglong2 eD = ep[3];
            asm("fma.rn.f32x2 %0, %1, %2, %0;" : "+l"(a0[0]) : "l"(xd0), "l"(eA.x));
            asm("fma.rn.f32x2 %0, %1, %2, %0;" : "+l"(a1[0]) : "l"(xd1), "l"(eA.x));
            asm("fma.rn.f32x2 %0, %1, %2, %0;" : "+l"(a0[1]) : "l"(xd0), "l"(eA.y));
            asm("fma.rn.f32x2 %0, %1, %2, %0;" : "+l"(a1[1]) : "l"(xd1), "l"(eA.y));
            asm("fma.rn.f32x2 %0, %1, %2, %0;" : "+l"(a0[2]) : "l"(xd0), "l"(eB.x));
            asm("fma.rn.f32x2 %0, %1, %2, %0;" : "+l"(a1[2]) : "l"(xd1), "l"(eB.x));
            asm("fma.rn.f32x2 %0, %1, %2, %0;" : "+l"(a0[3]) : "l"(xd0), "l"(eB.y));
            asm("fma.rn.f32x2 %0, %1, %2, %0;" : "+l"(a1[3]) : "l"(xd1), "l"(eB.y));
            asm("fma.rn.f32x2 %0, %1, %2, %0;" : "+l"(a0[4]) : "l"(xd0), "l"(eC.x));
            asm("fma.rn.f32x2 %0, %1, %2, %0;" : "+l"(a1[4]) : "l"(xd1), "l"(eC.x));
            asm("fma.rn.f32x2 %0, %1, %2, %0;" : "+l"(a0[5]) : "l"(xd0), "l"(eC.y));
            asm("fma.rn.f32x2 %0, %1, %2, %0;" : "+l"(a1[5]) : "l"(xd1), "l"(eC.y));
            asm("fma.rn.f32x2 %0, %1, %2, %0;" : "+l"(a0[6]) : "l"(xd0), "l"(eD.x));
            asm("fma.rn.f32x2 %0, %1, %2, %0;" : "+l"(a1[6]) : "l"(xd1), "l"(eD.x));
            asm("fma.rn.f32x2 %0, %1, %2, %0;" : "+l"(a0[7]) : "l"(xd0), "l"(eD.y));
            asm("fma.rn.f32x2 %0, %1, %2, %0;" : "+l"(a1[7]) : "l"(xd1), "l"(eD.y));
        }

#pragma unroll
        for (int q = 0; q < 8; q++) {
            float lo, hi;
            int kk = k0 + 2 * q;
            asm("mov.b64 {%0, %1}, %2;" : "=f"(lo), "=f"(hi) : "l"(a0[q]));
            if (lo > best0)      { sec0 = best0; bidx20 = bidx0; best0 = lo; bidx0 = kk; }
            else if (lo > sec0)  { sec0 = lo;    bidx20 = kk; }
            if (hi > best0)      { sec0 = best0; bidx20 = bidx0; best0 = hi; bidx0 = kk + 1; }
            else if (hi > sec0)  { sec0 = hi;    bidx20 = kk + 1; }
            asm("mov.b64 {%0, %1}, %2;" : "=f"(lo), "=f"(hi) : "l"(a1[q]));
            if (lo > best1)      { sec1 = best1; bidx21 = bidx1; best1 = lo; bidx1 = kk; }
            else if (lo > sec1)  { sec1 = lo;    bidx21 = kk; }
            if (hi > best1)      { sec1 = best1; bidx21 = bidx1; best1 = hi; bidx1 = kk + 1; }
            else if (hi > sec1)  { sec1 = hi;    bidx21 = kk + 1; }
        }
    }

    // Near-tie refinement (fp64 on fp32-rounded normalized x) — rare path.
    if (v0 && best0 - sec0 < 1e-4f * xn0) {
        double s1 = 0.0, s2 = 0.0;
#pragma unroll
        for (int d = 0; d < DC; d++) {
            float xh = __fdiv_rn(x0[d], xn0);
            s1 += (double)xh * (double)embT[d * KC + bidx0];
            s2 += (double)xh * (double)embT[d * KC + bidx20];
        }
        if (s2 > s1 || (s2 == s1 && bidx20 < bidx0)) bidx0 = bidx20;
    }
    if (v1 && best1 - sec1 < 1e-4f * xn1) {
        double s1 = 0.0, s2 = 0.0;
#pragma unroll
        for (int d = 0; d < DC; d++) {
            float xh = __fdiv_rn(x1[d], xn1);
            s1 += (double)xh * (double)embT[d * KC + bidx1];
            s2 += (double)xh * (double)embT[d * KC + bidx21];
        }
        if (s2 > s1 || (s2 == s1 && bidx21 < bidx1)) bidx1 = bidx21;
    }

    // label-picked cosines
    float picked = 0.f;
    if (v0) {
        int lab = max(0, min(KC - 1, labels[row0]));
        float yl = 0.f;
#pragma unroll
        for (int d = 0; d < DC; d++) yl = fmaf(x0[d], embT[d * KC + lab], yl);
        picked += yl / xn0;
    }
    if (v1) {
        int lab = max(0, min(KC - 1, labels[row1]));
        float yl = 0.f;
#pragma unroll
        for (int d = 0; d < DC; d++) yl = fmaf(x1[d], embT[d * KC + lab], yl);
        picked += yl / xn1;
    }

    // indices (coalesced)
    if (offI + N <= outTotal) {
        if (v0) out[offI + row0] = (float)bidx0;
        if (v1) out[offI + row1] = (float)bidx1;
    }

    sbidx[tid]       = bidx0;
    sbidx[tid + TPB] = bidx1;
    __syncthreads();

    const int rowsInBlk = (int)min((long long)RPB, (long long)N - rowBase);

    // ---- Block-cooperative coalesced output streaming ----
    if (offQ + (long long)N * DC <= outTotal) {
        long long qbase = offQ + rowBase * DC;
        const int total = rowsInBlk * DC;
#pragma unroll 4
        for (int j = tid; j < total; j += TPB) {
            int r = j >> 6;
            int d = j & 63;
            out[qbase + j] = __ldg(&emb[sbidx[r] * DC + d]);
        }
    }
    if (offE + (long long)N * KC <= outTotal) {
        long long ebase = offE + rowBase * KC;
        float2* eo2 = reinterpret_cast<float2*>(out + ebase);
        const int total2 = rowsInBlk * KC / 2;
#pragma unroll 4
        for (int j = tid; j < total2; j += TPB) {
            int r = j >> 8;
            int c = (j & 255) << 1;
            int b = sbidx[r];
            float2 v;
            v.x = (c     == b) ? 1.0f : 0.0f;
            v.y = (c + 1 == b) ? 1.0f : 0.0f;
            eo2[j] = v;
        }
    }

    // Deterministic block reduction of picked sums
    sred[tid] = picked;
    __syncthreads();
#pragma unroll
    for (int s = TPB / 2; s > 0; s >>= 1) {
        if (tid < s) sred[tid] += sred[tid + s];
        __syncthreads();
    }
    if (tid == 0) g_partials[blockIdx.x] = sred[0];
}

// ---------------------------------------------------------------------------
// Kernel 3: finalize
// ---------------------------------------------------------------------------
__global__ void vq_fin(float* __restrict__ out, long long offP, int nblocks,
                       int N, long long outTotal) {
    __shared__ double sh[1024];
    int t = threadIdx.x;
    double v = 0.0;
    for (int i = t; i < nblocks; i += 1024) v += (double)g_partials[i];
    sh[t] = v;
    __syncthreads();
    for (int s = 512; s > 0; s >>= 1) {
        if (t < s) sh[t] += sh[t + s];
        __syncthreads();
    }
    if (t == 0) {
        if (outTotal > 0)    out[0]    = (float)(1.0 - sh[0] / (double)N);
        if (offP < outTotal) out[offP] = 1.0f;
    }
}

// ---------------------------------------------------------------------------
extern "C" void kernel_launch(void* const* d_in, const int* in_sizes, int n_in,
                              void* d_out, int out_size) {
    const float* xin    = (const float*)d_in[0];
    const int*   labels = (const int*)d_in[1];
    const float* emb    = (const float*)d_in[2];
    float*       out    = (float*)d_out;

    int N = in_sizes[1];
    (void)n_in;

    long long outTotal = (long long)out_size;
    long long offQ = 1;
    long long offP = offQ + (long long)N * DC;
    long long offE = offP + 1;
    long long offI = offE + (long long)N * KC;

    int grid = (N + RPB - 1) / RPB;              // 512 blocks
    int smem = KC * DC * (int)sizeof(float);     // 131072 B

    cudaFuncSetAttribute(vq_main, cudaFuncAttributeMaxDynamicSharedMemorySize, smem);

    vq_prep<<<(KC + 127) / 128, 128>>>(emb);
    vq_main<<<grid, TPB, smem>>>(xin, labels, emb, out, N, offQ, offE, offI, outTotal);
    vq_fin<<<1, 1024>>>(out, offP, grid, N, outTotal);
}